// round 10
// baseline (speedup 1.0000x reference)
#include <cuda_runtime.h>
#include <cstdint>

#define FULL 0xffffffffu

constexpr int WPB = 4;   // warps per block

typedef unsigned long long u64t;

#define FMA2(d, a, b, c) \
    asm("fma.rn.f32x2 %0, %1, %2, %3;" : "=l"(d) : "l"(a), "l"(b), "l"(c))

__device__ __forceinline__ u64t pack2(float lo, float hi) {
    u64t r; asm("mov.b64 %0, {%1, %2};" : "=l"(r) : "f"(lo), "f"(hi)); return r;
}
__device__ __forceinline__ void unpack2(u64t p, float& lo, float& hi) {
    asm("mov.b64 {%0, %1}, %2;" : "=f"(lo), "=f"(hi) : "l"(p));
}

__device__ __forceinline__ float warpSum(float v) {
    v += __shfl_xor_sync(FULL, v, 16);
    v += __shfl_xor_sync(FULL, v, 8);
    v += __shfl_xor_sync(FULL, v, 4);
    v += __shfl_xor_sync(FULL, v, 2);
    v += __shfl_xor_sync(FULL, v, 1);
    return v;
}
__device__ __forceinline__ float warpMin(float v) {
    #pragma unroll
    for (int o = 16; o > 0; o >>= 1) v = fminf(v, __shfl_xor_sync(FULL, v, o));
    return v;
}

// One warp per molecule.
// Phase 1: Gram C = G G^T via GEMM-style 2D tiling: lane (r,c) owns a 4x8
//          C-tile. G chunks staged TRANSPOSED in shared (Gt[f][row]); per
//          feature 3 distinct-address LDS.128 (1 wavefront each) feed 16
//          packed FFMA2. ~5x fewer shared wavefronts than broadcast rows.
// Bridge:  one shared transpose rebuilds packed row-per-lane A2[16].
// Phase 2: Householder tridiag (identical to R8), f32x2 packed rows.
// Phase 3: Sturm bisection on [0, min diag(T)], 3 rounds of 32 probes.
__global__ __launch_bounds__(128, 5) void corr_eig_kernel(
    const float* __restrict__ sr, float* __restrict__ out, int M)
{
    // shBuf: phase-1 Gt[32 feats][32 rows] (4KB) then Af[32][36] (4.5KB) -- disjoint lifetimes
    __shared__ __align__(16) float  shBuf[WPB][32 * 36];
    __shared__ __align__(16) float  shV[WPB][2][32];    // double-buffered
    __shared__ __align__(16) float  shW[WPB][2][32];
    __shared__ __align__(16) float2 shDE[WPB][32];

    const int w    = threadIdx.x >> 5;
    const int lane = threadIdx.x & 31;
    const int mol  = blockIdx.x * WPB + w;
    if (mol >= M) return;

    float* Gt = shBuf[w];
    const int r = lane & 7;        // row-group: rows 4r..4r+3
    const int c = lane >> 3;       // col-group: cols 8c..8c+7

    // ---------------- Phase 1: tiled Gram ----------------
    u64t c2[4][4];                 // c2[i][t] = (C[4r+i][8c+2t], C[4r+i][8c+2t+1])
    #pragma unroll
    for (int i = 0; i < 4; i++)
        #pragma unroll
        for (int t = 0; t < 4; t++) c2[i][t] = 0ull;

    const float4* g4 =
        reinterpret_cast<const float4*>(sr) + ((size_t)mol * 32 + lane) * 32;

    #pragma unroll 1
    for (int ch = 0; ch < 4; ch++) {
        float4 xv[8];                          // own 32-feat chunk (row `lane`)
        #pragma unroll
        for (int i = 0; i < 8; i++) xv[i] = g4[ch * 8 + i];

        __syncwarp();                          // prior chunk's reads done
        // store transposed: Gt[f][lane], banks = lane -> conflict-free
        #pragma unroll
        for (int i = 0; i < 8; i++) {
            Gt[(4 * i + 0) * 32 + lane] = xv[i].x;
            Gt[(4 * i + 1) * 32 + lane] = xv[i].y;
            Gt[(4 * i + 2) * 32 + lane] = xv[i].z;
            Gt[(4 * i + 3) * 32 + lane] = xv[i].w;
        }
        __syncwarp();

        #pragma unroll 1
        for (int fg = 0; fg < 4; fg++) {
            #pragma unroll
            for (int fi = 0; fi < 8; fi++) {
                const int f = fg * 8 + fi;
                float4 av = *reinterpret_cast<const float4*>(&Gt[f * 32 + 4 * r]);
                ulonglong2 bA =
                    *reinterpret_cast<const ulonglong2*>(&Gt[f * 32 + 8 * c]);
                ulonglong2 bB =
                    *reinterpret_cast<const ulonglong2*>(&Gt[f * 32 + 8 * c + 4]);
                u64t ad0 = pack2(av.x, av.x), ad1 = pack2(av.y, av.y);
                u64t ad2 = pack2(av.z, av.z), ad3 = pack2(av.w, av.w);
                FMA2(c2[0][0], ad0, bA.x, c2[0][0]);
                FMA2(c2[0][1], ad0, bA.y, c2[0][1]);
                FMA2(c2[0][2], ad0, bB.x, c2[0][2]);
                FMA2(c2[0][3], ad0, bB.y, c2[0][3]);
                FMA2(c2[1][0], ad1, bA.x, c2[1][0]);
                FMA2(c2[1][1], ad1, bA.y, c2[1][1]);
                FMA2(c2[1][2], ad1, bB.x, c2[1][2]);
                FMA2(c2[1][3], ad1, bB.y, c2[1][3]);
                FMA2(c2[2][0], ad2, bA.x, c2[2][0]);
                FMA2(c2[2][1], ad2, bA.y, c2[2][1]);
                FMA2(c2[2][2], ad2, bB.x, c2[2][2]);
                FMA2(c2[2][3], ad2, bB.y, c2[2][3]);
                FMA2(c2[3][0], ad3, bA.x, c2[3][0]);
                FMA2(c2[3][1], ad3, bA.y, c2[3][1]);
                FMA2(c2[3][2], ad3, bB.x, c2[3][2]);
                FMA2(c2[3][3], ad3, bB.y, c2[3][3]);
            }
        }
    }

    // ---- Bridge: tile layout -> packed row-per-lane A2[16] via shared ----
    float* Af = Gt;                 // aliases Gt; Gt reads are done
    __syncwarp();
    #pragma unroll
    for (int i = 0; i < 4; i++) {
        ulonglong2 t0; t0.x = c2[i][0]; t0.y = c2[i][1];
        ulonglong2 t1; t1.x = c2[i][2]; t1.y = c2[i][3];
        *reinterpret_cast<ulonglong2*>(&Af[(4 * r + i) * 36 + 8 * c])     = t0;
        *reinterpret_cast<ulonglong2*>(&Af[(4 * r + i) * 36 + 8 * c + 4]) = t1;
    }
    __syncwarp();

    u64t A2[16];                    // packed row of C: (a_{2m}, a_{2m+1})
    #pragma unroll
    for (int q = 0; q < 8; q++) {
        ulonglong2 t = *reinterpret_cast<const ulonglong2*>(&Af[lane * 36 + 4 * q]);
        A2[2 * q] = t.x; A2[2 * q + 1] = t.y;
    }

    // ---------------- Phase 2: Householder tridiagonalization ----------------
    // Lane i owns row i (packed). Inactive lanes have v = w = 0: rows freeze.
    // sV/sW entries for j <= k are 0 -> packed over-reads contribute nothing.
    float d_reg = 0.f, e_reg = 0.f;

    #pragma unroll
    for (int k = 0; k < 30; k++) {
        const bool act = (lane > k);

        // sigma = sum_{j>k} a_j^2 (only lane k's value consumed)
        u64t S0 = 0ull, S1 = 0ull;
        if ((k & 1) == 0) {                      // pair k/2 holds (a_k, a_{k+1})
            u64t b = A2[k >> 1] & 0xFFFFFFFF00000000ull;   // keep a_{k+1}
            FMA2(S0, b, b, S0);
        }
        #pragma unroll
        for (int m = (k >> 1) + 1; m < 16; m++) {
            if (m & 1) { FMA2(S1, A2[m], A2[m], S1); }
            else       { FMA2(S0, A2[m], A2[m], S0); }
        }
        float s0l, s0h, s1l, s1h;
        unpack2(S0, s0l, s0h); unpack2(S1, s1l, s1h);
        float sig_loc = (s0l + s0h) + (s1l + s1h);

        // own a_k, a_{k+1} (static extraction)
        float ak, ak1;
        if ((k & 1) == 0) {
            unpack2(A2[k >> 1], ak, ak1);
        } else {
            float t0, t1;
            unpack2(A2[k >> 1], t0, ak);
            unpack2(A2[(k >> 1) + 1], ak1, t1);
        }

        float sigma = __shfl_sync(FULL, sig_loc, k);
        float x1    = __shfl_sync(FULL, ak1, k);       // A[k][k+1]

        float alpha = -copysignf(sqrtf(sigma), x1);
        bool  ok    = (sigma > 1e-20f);
        float beta  = ok ? 1.0f / (sigma - alpha * x1) : 0.f;   // 2 / v^T v
        if (lane == k) { d_reg = ak; e_reg = ok ? alpha : x1; }

        float v = act ? ak : 0.f;
        if (lane == k + 1) v = ok ? (x1 - alpha) : 0.f;

        float* sV = shV[w][k & 1];
        float* sW = shW[w][k & 1];
        sV[lane] = v;
        __syncwarp();

        // p = beta * (A v): packed dot, V read as 2 packed pairs per LDS.128
        u64t P0 = 0ull, P1 = 0ull;
        #pragma unroll
        for (int jq = (k + 1) >> 2; jq < 8; jq++) {
            ulonglong2 V2 = *reinterpret_cast<const ulonglong2*>(&sV[4 * jq]);
            FMA2(P0, A2[2 * jq],     V2.x, P0);
            FMA2(P1, A2[2 * jq + 1], V2.y, P1);
        }
        float p0l, p0h, p1l, p1h;
        unpack2(P0, p0l, p0h); unpack2(P1, p1l, p1h);
        float p = (p0l + p0h) + (p1l + p1h);
        p = act ? p * beta : 0.f;

        float s  = warpSum(p * v);                     // p^T v
        float wv = p - (0.5f * beta * s) * v;          // 0 on inactive lanes

        sW[lane] = wv;
        __syncwarp();

        // A <- A - v w^T - w v^T   (packed: 2 FFMA2 per pair)
        u64t nv2 = pack2(-v, -v), nw2 = pack2(-wv, -wv);
        #pragma unroll
        for (int jq = (k + 1) >> 2; jq < 8; jq++) {
            ulonglong2 V2 = *reinterpret_cast<const ulonglong2*>(&sV[4 * jq]);
            ulonglong2 W2 = *reinterpret_cast<const ulonglong2*>(&sW[4 * jq]);
            u64t t;
            FMA2(t, nw2, V2.x, A2[2 * jq]);
            FMA2(A2[2 * jq], nv2, W2.x, t);
            FMA2(t, nw2, V2.y, A2[2 * jq + 1]);
            FMA2(A2[2 * jq + 1], nv2, W2.y, t);
        }
    }
    if (lane == 30) unpack2(A2[15], d_reg, e_reg);     // a30, a31
    if (lane == 31) { float t; unpack2(A2[15], t, d_reg); e_reg = 0.f; }

    // ---------------- Phase 3: Sturm bisection ----------------
    // C is PSD => lambda_min in [0, min_i T_ii].
    __syncwarp();
    shDE[w][lane] = make_float2(d_reg, e_reg * e_reg);
    __syncwarp();
    const float4* DE4 = reinterpret_cast<const float4*>(shDE[w]);  // (d,e2)

    float lo = 0.f;
    float hi = warpMin(d_reg) * 1.0001f;

    #pragma unroll 1
    for (int rr = 0; rr < 3; rr++) {
        float h = (hi - lo) * (1.0f / 33.0f);
        float x = fmaf(h, (float)(lane + 1), lo);

        float4 t = DE4[0];                       // d0, e2_0, d1, e2_1
        float q   = t.x - x;
        int   cnt = (q < 0.f);
        float eprev = t.y;
        {
            float qn = (t.z - x) - __fdividef(eprev, q);
            if (qn == 0.f) qn = -1e-30f;
            cnt += (qn < 0.f);
            q = qn; eprev = t.w;
        }
        #pragma unroll
        for (int m = 1; m < 16; m++) {
            t = DE4[m];
            float qn = (t.x - x) - __fdividef(eprev, q);
            if (qn == 0.f) qn = -1e-30f;
            cnt += (qn < 0.f);
            q = qn; eprev = t.y;

            qn = (t.z - x) - __fdividef(eprev, q);
            if (qn == 0.f) qn = -1e-30f;
            cnt += (qn < 0.f);
            q = qn; eprev = t.w;
        }

        unsigned mask = __ballot_sync(FULL, cnt >= 1);
        int j0 = mask ? (__ffs(mask) - 1) : 32;
        lo += h * (float)j0;
        hi  = lo + h;
    }

    if (lane == 0) out[mol] = 0.5f * (lo + hi);
}

extern "C" void kernel_launch(void* const* d_in, const int* in_sizes, int n_in,
                              void* d_out, int out_size) {
    const float* sr = (const float*)d_in[0];
    // d_in[1] (idx_m) unused: uniform groups -> [M, 32, 128]
    float* out = (float*)d_out;
    int M = in_sizes[0] >> 12;   // / (32*128)

    int blocks = (M + WPB - 1) / WPB;
    corr_eig_kernel<<<blocks, 128>>>(sr, out, M);
}

// round 11
// speedup vs baseline: 1.0074x; 1.0074x over previous
#include <cuda_runtime.h>
#include <cstdint>

#define FULL 0xffffffffu

constexpr int WPB = 4;   // warps per block

typedef unsigned long long u64t;

#define FMA2(d, a, b, c) \
    asm("fma.rn.f32x2 %0, %1, %2, %3;" : "=l"(d) : "l"(a), "l"(b), "l"(c))

__device__ __forceinline__ u64t pack2(float lo, float hi) {
    u64t r; asm("mov.b64 %0, {%1, %2};" : "=l"(r) : "f"(lo), "f"(hi)); return r;
}
__device__ __forceinline__ void unpack2(u64t p, float& lo, float& hi) {
    asm("mov.b64 {%0, %1}, %2;" : "=f"(lo), "=f"(hi) : "l"(p));
}

__device__ __forceinline__ float warpSum(float v) {
    v += __shfl_xor_sync(FULL, v, 16);
    v += __shfl_xor_sync(FULL, v, 8);
    v += __shfl_xor_sync(FULL, v, 4);
    v += __shfl_xor_sync(FULL, v, 2);
    v += __shfl_xor_sync(FULL, v, 1);
    return v;
}
__device__ __forceinline__ float warpMin(float v) {
    #pragma unroll
    for (int o = 16; o > 0; o >>= 1) v = fminf(v, __shfl_xor_sync(FULL, v, o));
    return v;
}

// One warp per molecule.
// Phase 1: Gram C = G G^T, GEMM-style 4x8 tile per lane. Global data is
//          streamed straight into a transposed shared tile (no register
//          staging buffer -> low pressure, clean FFMA2 register pairs).
//          Per feature: 3 distinct-address LDS.128 + 16 packed FFMA2.
// Bridge:  one shared round-trip rebuilds packed row-per-lane A2[16].
// Phase 2: Householder tridiag (identical to R8), f32x2 packed rows.
// Phase 3: Sturm bisection on [0, min diag(T)], 3 rounds of 32 probes.
__global__ __launch_bounds__(128, 6) void corr_eig_kernel(
    const float* __restrict__ sr, float* __restrict__ out, int M)
{
    // shBuf: phase-1 Gt[32 feats][32 rows] (4KB), then Af[32][36] (4.5KB)
    __shared__ __align__(16) float  shBuf[WPB][32 * 36];
    __shared__ __align__(16) float  shV[WPB][2][32];    // double-buffered
    __shared__ __align__(16) float  shW[WPB][2][32];
    __shared__ __align__(16) float2 shDE[WPB][32];

    const int w    = threadIdx.x >> 5;
    const int lane = threadIdx.x & 31;
    const int mol  = blockIdx.x * WPB + w;
    if (mol >= M) return;

    float* Gt = shBuf[w];
    const int r = lane & 7;        // row-group: rows 4r..4r+3
    const int c = lane >> 3;       // col-group: cols 8c..8c+7

    // ---------------- Phase 1: tiled Gram ----------------
    u64t c2[16];                   // c2[4*i+t] = (C[4r+i][8c+2t], C[4r+i][8c+2t+1])
    #pragma unroll
    for (int i = 0; i < 16; i++) c2[i] = 0ull;

    const float4* g4 =
        reinterpret_cast<const float4*>(sr) + ((size_t)mol * 32 + lane) * 32;

    #pragma unroll 1
    for (int ch = 0; ch < 4; ch++) {
        __syncwarp();                          // prior chunk's reads done
        // stream global -> transposed shared (no register staging)
        #pragma unroll
        for (int i = 0; i < 8; i++) {
            float4 x = g4[ch * 8 + i];
            Gt[(4 * i + 0) * 32 + lane] = x.x;
            Gt[(4 * i + 1) * 32 + lane] = x.y;
            Gt[(4 * i + 2) * 32 + lane] = x.z;
            Gt[(4 * i + 3) * 32 + lane] = x.w;
        }
        __syncwarp();

        #pragma unroll 1
        for (int fg = 0; fg < 4; fg++) {
            #pragma unroll
            for (int fi = 0; fi < 8; fi++) {
                const float* base = &Gt[(fg * 8 + fi) * 32];
                float4 av = *reinterpret_cast<const float4*>(base + 4 * r);
                ulonglong2 bA =
                    *reinterpret_cast<const ulonglong2*>(base + 8 * c);
                ulonglong2 bB =
                    *reinterpret_cast<const ulonglong2*>(base + 8 * c + 4);
                u64t ad0 = pack2(av.x, av.x), ad1 = pack2(av.y, av.y);
                u64t ad2 = pack2(av.z, av.z), ad3 = pack2(av.w, av.w);
                FMA2(c2[0],  ad0, bA.x, c2[0]);
                FMA2(c2[1],  ad0, bA.y, c2[1]);
                FMA2(c2[2],  ad0, bB.x, c2[2]);
                FMA2(c2[3],  ad0, bB.y, c2[3]);
                FMA2(c2[4],  ad1, bA.x, c2[4]);
                FMA2(c2[5],  ad1, bA.y, c2[5]);
                FMA2(c2[6],  ad1, bB.x, c2[6]);
                FMA2(c2[7],  ad1, bB.y, c2[7]);
                FMA2(c2[8],  ad2, bA.x, c2[8]);
                FMA2(c2[9],  ad2, bA.y, c2[9]);
                FMA2(c2[10], ad2, bB.x, c2[10]);
                FMA2(c2[11], ad2, bB.y, c2[11]);
                FMA2(c2[12], ad3, bA.x, c2[12]);
                FMA2(c2[13], ad3, bA.y, c2[13]);
                FMA2(c2[14], ad3, bB.x, c2[14]);
                FMA2(c2[15], ad3, bB.y, c2[15]);
            }
        }
    }

    // ---- Bridge: tile layout -> packed row-per-lane A2[16] via shared ----
    float* Af = Gt;                 // aliases Gt; Gt reads are done
    __syncwarp();
    #pragma unroll
    for (int i = 0; i < 4; i++) {
        ulonglong2 t0; t0.x = c2[4 * i + 0]; t0.y = c2[4 * i + 1];
        ulonglong2 t1; t1.x = c2[4 * i + 2]; t1.y = c2[4 * i + 3];
        *reinterpret_cast<ulonglong2*>(&Af[(4 * r + i) * 36 + 8 * c])     = t0;
        *reinterpret_cast<ulonglong2*>(&Af[(4 * r + i) * 36 + 8 * c + 4]) = t1;
    }
    __syncwarp();

    u64t A2[16];                    // packed row of C: (a_{2m}, a_{2m+1})
    #pragma unroll
    for (int q = 0; q < 8; q++) {
        ulonglong2 t = *reinterpret_cast<const ulonglong2*>(&Af[lane * 36 + 4 * q]);
        A2[2 * q] = t.x; A2[2 * q + 1] = t.y;
    }

    // ---------------- Phase 2: Householder tridiagonalization ----------------
    // Lane i owns row i (packed). Inactive lanes have v = w = 0: rows freeze.
    // sV/sW entries for j <= k are 0 -> packed over-reads contribute nothing.
    float d_reg = 0.f, e_reg = 0.f;

    #pragma unroll
    for (int k = 0; k < 30; k++) {
        const bool act = (lane > k);

        // sigma = sum_{j>k} a_j^2 (only lane k's value consumed)
        u64t S0 = 0ull, S1 = 0ull;
        if ((k & 1) == 0) {                      // pair k/2 holds (a_k, a_{k+1})
            u64t b = A2[k >> 1] & 0xFFFFFFFF00000000ull;   // keep a_{k+1}
            FMA2(S0, b, b, S0);
        }
        #pragma unroll
        for (int m = (k >> 1) + 1; m < 16; m++) {
            if (m & 1) { FMA2(S1, A2[m], A2[m], S1); }
            else       { FMA2(S0, A2[m], A2[m], S0); }
        }
        float s0l, s0h, s1l, s1h;
        unpack2(S0, s0l, s0h); unpack2(S1, s1l, s1h);
        float sig_loc = (s0l + s0h) + (s1l + s1h);

        // own a_k, a_{k+1} (static extraction)
        float ak, ak1;
        if ((k & 1) == 0) {
            unpack2(A2[k >> 1], ak, ak1);
        } else {
            float t0, t1;
            unpack2(A2[k >> 1], t0, ak);
            unpack2(A2[(k >> 1) + 1], ak1, t1);
        }

        float sigma = __shfl_sync(FULL, sig_loc, k);
        float x1    = __shfl_sync(FULL, ak1, k);       // A[k][k+1]

        float alpha = -copysignf(sqrtf(sigma), x1);
        bool  ok    = (sigma > 1e-20f);
        float beta  = ok ? 1.0f / (sigma - alpha * x1) : 0.f;   // 2 / v^T v
        if (lane == k) { d_reg = ak; e_reg = ok ? alpha : x1; }

        float v = act ? ak : 0.f;
        if (lane == k + 1) v = ok ? (x1 - alpha) : 0.f;

        float* sV = shV[w][k & 1];
        float* sW = shW[w][k & 1];
        sV[lane] = v;
        __syncwarp();

        // p = beta * (A v): packed dot, V read as 2 packed pairs per LDS.128
        u64t P0 = 0ull, P1 = 0ull;
        #pragma unroll
        for (int jq = (k + 1) >> 2; jq < 8; jq++) {
            ulonglong2 V2 = *reinterpret_cast<const ulonglong2*>(&sV[4 * jq]);
            FMA2(P0, A2[2 * jq],     V2.x, P0);
            FMA2(P1, A2[2 * jq + 1], V2.y, P1);
        }
        float p0l, p0h, p1l, p1h;
        unpack2(P0, p0l, p0h); unpack2(P1, p1l, p1h);
        float p = (p0l + p0h) + (p1l + p1h);
        p = act ? p * beta : 0.f;

        float s  = warpSum(p * v);                     // p^T v
        float wv = p - (0.5f * beta * s) * v;          // 0 on inactive lanes

        sW[lane] = wv;
        __syncwarp();

        // A <- A - v w^T - w v^T   (packed: 2 FFMA2 per pair)
        u64t nv2 = pack2(-v, -v), nw2 = pack2(-wv, -wv);
        #pragma unroll
        for (int jq = (k + 1) >> 2; jq < 8; jq++) {
            ulonglong2 V2 = *reinterpret_cast<const ulonglong2*>(&sV[4 * jq]);
            ulonglong2 W2 = *reinterpret_cast<const ulonglong2*>(&sW[4 * jq]);
            u64t t;
            FMA2(t, nw2, V2.x, A2[2 * jq]);
            FMA2(A2[2 * jq], nv2, W2.x, t);
            FMA2(t, nw2, V2.y, A2[2 * jq + 1]);
            FMA2(A2[2 * jq + 1], nv2, W2.y, t);
        }
    }
    if (lane == 30) unpack2(A2[15], d_reg, e_reg);     // a30, a31
    if (lane == 31) { float t; unpack2(A2[15], t, d_reg); e_reg = 0.f; }

    // ---------------- Phase 3: Sturm bisection ----------------
    // C is PSD => lambda_min in [0, min_i T_ii].
    __syncwarp();
    shDE[w][lane] = make_float2(d_reg, e_reg * e_reg);
    __syncwarp();
    const float4* DE4 = reinterpret_cast<const float4*>(shDE[w]);  // (d,e2)

    float lo = 0.f;
    float hi = warpMin(d_reg) * 1.0001f;

    #pragma unroll 1
    for (int rr = 0; rr < 3; rr++) {
        float h = (hi - lo) * (1.0f / 33.0f);
        float x = fmaf(h, (float)(lane + 1), lo);

        float4 t = DE4[0];                       // d0, e2_0, d1, e2_1
        float q   = t.x - x;
        int   cnt = (q < 0.f);
        float eprev = t.y;
        {
            float qn = (t.z - x) - __fdividef(eprev, q);
            if (qn == 0.f) qn = -1e-30f;
            cnt += (qn < 0.f);
            q = qn; eprev = t.w;
        }
        #pragma unroll
        for (int m = 1; m < 16; m++) {
            t = DE4[m];
            float qn = (t.x - x) - __fdividef(eprev, q);
            if (qn == 0.f) qn = -1e-30f;
            cnt += (qn < 0.f);
            q = qn; eprev = t.y;

            qn = (t.z - x) - __fdividef(eprev, q);
            if (qn == 0.f) qn = -1e-30f;
            cnt += (qn < 0.f);
            q = qn; eprev = t.w;
        }

        unsigned mask = __ballot_sync(FULL, cnt >= 1);
        int j0 = mask ? (__ffs(mask) - 1) : 32;
        lo += h * (float)j0;
        hi  = lo + h;
    }

    if (lane == 0) out[mol] = 0.5f * (lo + hi);
}

extern "C" void kernel_launch(void* const* d_in, const int* in_sizes, int n_in,
                              void* d_out, int out_size) {
    const float* sr = (const float*)d_in[0];
    // d_in[1] (idx_m) unused: uniform groups -> [M, 32, 128]
    float* out = (float*)d_out;
    int M = in_sizes[0] >> 12;   // / (32*128)

    int blocks = (M + WPB - 1) / WPB;
    corr_eig_kernel<<<blocks, 128>>>(sr, out, M);
}

// round 12
// speedup vs baseline: 1.1794x; 1.1708x over previous
#include <cuda_runtime.h>
#include <cstdint>

#define FULL 0xffffffffu

constexpr int WPB = 4;        // warps per block
constexpr int MAXM = 8192;    // molecules (fixed problem shape)

typedef unsigned long long u64t;

#define FMA2(d, a, b, c) \
    asm("fma.rn.f32x2 %0, %1, %2, %3;" : "=l"(d) : "l"(a), "l"(b), "l"(c))
#define ADD2(d, a, b) \
    asm("add.rn.f32x2 %0, %1, %2;" : "=l"(d) : "l"(a), "l"(b))

__device__ __forceinline__ u64t pack2(float lo, float hi) {
    u64t r; asm("mov.b64 %0, {%1, %2};" : "=l"(r) : "f"(lo), "f"(hi)); return r;
}
__device__ __forceinline__ void unpack2(u64t p, float& lo, float& hi) {
    asm("mov.b64 {%0, %1}, %2;" : "=f"(lo), "=f"(hi) : "l"(p));
}

__device__ __forceinline__ float warpSum(float v) {
    v += __shfl_xor_sync(FULL, v, 16);
    v += __shfl_xor_sync(FULL, v, 8);
    v += __shfl_xor_sync(FULL, v, 4);
    v += __shfl_xor_sync(FULL, v, 2);
    v += __shfl_xor_sync(FULL, v, 1);
    return v;
}
__device__ __forceinline__ float warpMin(float v) {
    #pragma unroll
    for (int o = 16; o > 0; o >>= 1) v = fminf(v, __shfl_xor_sync(FULL, v, o));
    return v;
}

// Inter-kernel scratch: packed Gram rows. Layout: [mol][q(0..7)][lane] of
// ulonglong2 (= floats a_{4q}..a_{4q+3} of row `lane`). 32 MB static.
__device__ ulonglong2 g_C[(size_t)MAXM * 8 * 32];

// ============================ Kernel A: Gram ============================
// One warp per molecule. R8 phase-1: 4 x 32-feat chunks staged in shared,
// broadcast LDS.128 row reads, packed f32x2 FMA. Row of C -> packed A2[16],
// then streamed to global scratch (coalesced STG.128).
__global__ __launch_bounds__(128, 6) void gram_kernel(
    const float* __restrict__ sr, int M)
{
    __shared__ __align__(16) float shG[WPB][32 * 36];   // stride 36: CF stores

    const int w    = threadIdx.x >> 5;
    const int lane = threadIdx.x & 31;
    const int mol  = blockIdx.x * WPB + w;
    if (mol >= M || mol >= MAXM) return;

    float* G = shG[w];

    u64t A2[16];                               // packed row: (a_{2m}, a_{2m+1})
    #pragma unroll
    for (int m = 0; m < 16; m++) A2[m] = 0ull;

    const ulonglong2* g2 =
        reinterpret_cast<const ulonglong2*>(sr) + ((size_t)mol * 32 + lane) * 32;

    #pragma unroll 1
    for (int c = 0; c < 4; c++) {
        ulonglong2 xv[8];                      // own 32-feat chunk
        #pragma unroll
        for (int i = 0; i < 8; i++) xv[i] = g2[c * 8 + i];

        __syncwarp();                          // prior chunk reads done
        #pragma unroll
        for (int i = 0; i < 8; i++)
            *reinterpret_cast<ulonglong2*>(&G[lane * 36 + 4 * i]) = xv[i];
        __syncwarp();

        #pragma unroll 2
        for (int jp = 0; jp < 16; jp++) {      // pair of rows (2jp, 2jp+1)
            const float* r0 = &G[(2 * jp)     * 36];
            const float* r1 = &G[(2 * jp + 1) * 36];
            u64t acc0 = 0ull, acc1 = 0ull;
            #pragma unroll
            for (int i = 0; i < 8; i++) {
                ulonglong2 y0 = *reinterpret_cast<const ulonglong2*>(r0 + 4 * i);
                ulonglong2 y1 = *reinterpret_cast<const ulonglong2*>(r1 + 4 * i);
                FMA2(acc0, xv[i].x, y0.x, acc0);
                FMA2(acc0, xv[i].y, y0.y, acc0);
                FMA2(acc1, xv[i].x, y1.x, acc1);
                FMA2(acc1, xv[i].y, y1.y, acc1);
            }
            float u0, u1, v0, v1;
            unpack2(acc0, u0, u1);
            unpack2(acc1, v0, v1);
            u64t p = pack2(u0, v0), q = pack2(u1, v1), t;
            ADD2(t, p, q);
            ADD2(A2[jp], A2[jp], t);
        }
    }

    // Stream packed row to scratch (coalesced: warp writes 512B per q)
    ulonglong2* dst = &g_C[(size_t)mol * 8 * 32];
    #pragma unroll
    for (int q = 0; q < 8; q++) {
        ulonglong2 t; t.x = A2[2 * q]; t.y = A2[2 * q + 1];
        dst[q * 32 + lane] = t;
    }
}

// ================= Kernel B: Householder + Sturm bisection =================
// One warp per molecule; low register pressure -> high occupancy.
__global__ __launch_bounds__(128, 8) void eig_kernel(
    float* __restrict__ out, int M)
{
    __shared__ __align__(16) float  shV[WPB][2][32];    // double-buffered
    __shared__ __align__(16) float  shW[WPB][2][32];
    __shared__ __align__(16) float2 shDE[WPB][32];

    const int w    = threadIdx.x >> 5;
    const int lane = threadIdx.x & 31;
    const int mol  = blockIdx.x * WPB + w;
    if (mol >= M || mol >= MAXM) return;

    // Load packed row A2[16] (coalesced LDG.128)
    u64t A2[16];
    const ulonglong2* src = &g_C[(size_t)mol * 8 * 32];
    #pragma unroll
    for (int q = 0; q < 8; q++) {
        ulonglong2 t = src[q * 32 + lane];
        A2[2 * q] = t.x; A2[2 * q + 1] = t.y;
    }

    // ---------------- Householder tridiagonalization (== R8) ----------------
    float d_reg = 0.f, e_reg = 0.f;

    #pragma unroll
    for (int k = 0; k < 30; k++) {
        const bool act = (lane > k);

        // sigma = sum_{j>k} a_j^2 (only lane k's value consumed)
        u64t S0 = 0ull, S1 = 0ull;
        if ((k & 1) == 0) {                      // pair k/2 holds (a_k, a_{k+1})
            u64t b = A2[k >> 1] & 0xFFFFFFFF00000000ull;   // keep a_{k+1}
            FMA2(S0, b, b, S0);
        }
        #pragma unroll
        for (int m = (k >> 1) + 1; m < 16; m++) {
            if (m & 1) { FMA2(S1, A2[m], A2[m], S1); }
            else       { FMA2(S0, A2[m], A2[m], S0); }
        }
        float s0l, s0h, s1l, s1h;
        unpack2(S0, s0l, s0h); unpack2(S1, s1l, s1h);
        float sig_loc = (s0l + s0h) + (s1l + s1h);

        // own a_k, a_{k+1} (static extraction)
        float ak, ak1;
        if ((k & 1) == 0) {
            unpack2(A2[k >> 1], ak, ak1);
        } else {
            float t0, t1;
            unpack2(A2[k >> 1], t0, ak);
            unpack2(A2[(k >> 1) + 1], ak1, t1);
        }

        float sigma = __shfl_sync(FULL, sig_loc, k);
        float x1    = __shfl_sync(FULL, ak1, k);       // A[k][k+1]

        float alpha = -copysignf(sqrtf(sigma), x1);
        bool  ok    = (sigma > 1e-20f);
        float beta  = ok ? 1.0f / (sigma - alpha * x1) : 0.f;   // 2 / v^T v
        if (lane == k) { d_reg = ak; e_reg = ok ? alpha : x1; }

        float v = act ? ak : 0.f;
        if (lane == k + 1) v = ok ? (x1 - alpha) : 0.f;

        float* sV = shV[w][k & 1];
        float* sW = shW[w][k & 1];
        sV[lane] = v;
        __syncwarp();

        // p = beta * (A v): packed dot, V read as 2 packed pairs per LDS.128
        u64t P0 = 0ull, P1 = 0ull;
        #pragma unroll
        for (int jq = (k + 1) >> 2; jq < 8; jq++) {
            ulonglong2 V2 = *reinterpret_cast<const ulonglong2*>(&sV[4 * jq]);
            FMA2(P0, A2[2 * jq],     V2.x, P0);
            FMA2(P1, A2[2 * jq + 1], V2.y, P1);
        }
        float p0l, p0h, p1l, p1h;
        unpack2(P0, p0l, p0h); unpack2(P1, p1l, p1h);
        float p = (p0l + p0h) + (p1l + p1h);
        p = act ? p * beta : 0.f;

        float s  = warpSum(p * v);                     // p^T v
        float wv = p - (0.5f * beta * s) * v;          // 0 on inactive lanes

        sW[lane] = wv;
        __syncwarp();

        // A <- A - v w^T - w v^T   (packed: 2 FFMA2 per pair)
        u64t nv2 = pack2(-v, -v), nw2 = pack2(-wv, -wv);
        #pragma unroll
        for (int jq = (k + 1) >> 2; jq < 8; jq++) {
            ulonglong2 V2 = *reinterpret_cast<const ulonglong2*>(&sV[4 * jq]);
            ulonglong2 W2 = *reinterpret_cast<const ulonglong2*>(&sW[4 * jq]);
            u64t t;
            FMA2(t, nw2, V2.x, A2[2 * jq]);
            FMA2(A2[2 * jq], nv2, W2.x, t);
            FMA2(t, nw2, V2.y, A2[2 * jq + 1]);
            FMA2(A2[2 * jq + 1], nv2, W2.y, t);
        }
    }
    if (lane == 30) unpack2(A2[15], d_reg, e_reg);     // a30, a31
    if (lane == 31) { float t; unpack2(A2[15], t, d_reg); e_reg = 0.f; }

    // ---------------- Sturm bisection ----------------
    // C is PSD => lambda_min in [0, min_i T_ii].
    __syncwarp();
    shDE[w][lane] = make_float2(d_reg, e_reg * e_reg);
    __syncwarp();
    const float4* DE4 = reinterpret_cast<const float4*>(shDE[w]);  // (d,e2)

    float lo = 0.f;
    float hi = warpMin(d_reg) * 1.0001f;

    #pragma unroll 1
    for (int rr = 0; rr < 3; rr++) {
        float h = (hi - lo) * (1.0f / 33.0f);
        float x = fmaf(h, (float)(lane + 1), lo);

        float4 t = DE4[0];                       // d0, e2_0, d1, e2_1
        float q   = t.x - x;
        int   cnt = (q < 0.f);
        float eprev = t.y;
        {
            float qn = (t.z - x) - __fdividef(eprev, q);
            if (qn == 0.f) qn = -1e-30f;
            cnt += (qn < 0.f);
            q = qn; eprev = t.w;
        }
        #pragma unroll
        for (int m = 1; m < 16; m++) {
            t = DE4[m];
            float qn = (t.x - x) - __fdividef(eprev, q);
            if (qn == 0.f) qn = -1e-30f;
            cnt += (qn < 0.f);
            q = qn; eprev = t.y;

            qn = (t.z - x) - __fdividef(eprev, q);
            if (qn == 0.f) qn = -1e-30f;
            cnt += (qn < 0.f);
            q = qn; eprev = t.w;
        }

        unsigned mask = __ballot_sync(FULL, cnt >= 1);
        int j0 = mask ? (__ffs(mask) - 1) : 32;
        lo += h * (float)j0;
        hi  = lo + h;
    }

    if (lane == 0) out[mol] = 0.5f * (lo + hi);
}

extern "C" void kernel_launch(void* const* d_in, const int* in_sizes, int n_in,
                              void* d_out, int out_size) {
    const float* sr = (const float*)d_in[0];
    // d_in[1] (idx_m) unused: uniform groups -> [M, 32, 128]
    float* out = (float*)d_out;
    int M = in_sizes[0] >> 12;   // / (32*128)

    int blocks = (M + WPB - 1) / WPB;
    gram_kernel<<<blocks, 128>>>(sr, M);
    eig_kernel<<<blocks, 128>>>(out, M);
}